// round 1
// baseline (speedup 1.0000x reference)
#include <cuda_runtime.h>
#include <cuda_bf16.h>
#include <math.h>

// Problem constants
#define Bn 4
#define Tn 256
#define Un 64
#define U1 65
#define Vn 1024
#define Fn 80
#define Hn 512
#define Jn 512
#define NROWS (Bn*Tn*U1)   // 66560
#define NEGF (-1e30f)

// ---------------- scratch (static __device__, allocation-free) ----------------
__device__ float g_enc[Bn*Tn*Hn];               // (1024, 512)
__device__ float g_e  [Bn*Tn*Jn];               // (1024, 512)
__device__ float g_dec[Bn*U1*Hn];               // (260, 512)
__device__ float g_d  [Bn*U1*Jn];               // (260, 512)
__device__ __nv_bfloat16 g_Hbuf[(size_t)NROWS*Jn];  // 68MB: tanh(e+d+b_j) rows
__device__ float g_cmax[NROWS*8];
__device__ float g_csum[NROWS*8];
__device__ float g_l0[NROWS];
__device__ float g_lt[NROWS];
__device__ float g_blank[NROWS];                // (b,t,u) u in [0,64]
__device__ float g_lbl[Bn*Tn*Un];               // (b,t,u) u in [0,63], masked

__device__ __forceinline__ float lae(float a, float b){
    float m = fmaxf(a,b);
    return m + log1pf(__expf(fminf(a,b) - m));
}

// ---------------- generic small SGEMM: C(M,N) = A(M,K) @ B(K,N) ----------------
__global__ void sgemm64(const float* __restrict__ A, const float* __restrict__ B,
                        float* __restrict__ C, int M, int N, int K){
    __shared__ float As[16][64];
    __shared__ float Bs[16][64];
    int tid = threadIdx.x;
    int tx = tid & 15, ty = tid >> 4;
    int rowBase = blockIdx.y*64, colBase = blockIdx.x*64;
    float acc[4][4] = {};
    for(int k0=0;k0<K;k0+=16){
        for(int i=tid;i<64*16;i+=256){
            int m=i>>4, kk=i&15;
            int gm=rowBase+m, gk=k0+kk;
            As[kk][m] = (gm<M && gk<K) ? A[(size_t)gm*K+gk] : 0.f;
        }
        for(int i=tid;i<16*64;i+=256){
            int kk=i>>6, n=i&63;
            int gk=k0+kk, gn=colBase+n;
            Bs[kk][n] = (gk<K && gn<N) ? B[(size_t)gk*N+gn] : 0.f;
        }
        __syncthreads();
        #pragma unroll
        for(int kk=0;kk<16;kk++){
            float a[4],b[4];
            #pragma unroll
            for(int i=0;i<4;i++) a[i]=As[kk][ty*4+i];
            #pragma unroll
            for(int j=0;j<4;j++) b[j]=Bs[kk][tx*4+j];
            #pragma unroll
            for(int i=0;i<4;i++)
                #pragma unroll
                for(int j=0;j<4;j++) acc[i][j]=fmaf(a[i],b[j],acc[i][j]);
        }
        __syncthreads();
    }
    #pragma unroll
    for(int i=0;i<4;i++){
        int gm=rowBase+ty*4+i;
        if(gm<M)
            #pragma unroll
            for(int j=0;j<4;j++){
                int gn=colBase+tx*4+j;
                if(gn<N) C[(size_t)gm*N+gn]=acc[i][j];
            }
    }
}

// ---------------- gather decoder embedding rows ----------------
__global__ void gather_dec(const float* __restrict__ emb, const int* __restrict__ targets){
    int row = blockIdx.x;            // 0..259 = b*65+u
    int b = row / U1, u = row - b*U1;
    int tok = (u==0) ? 0 : targets[b*Un + (u-1)];
    const float* src = emb + (size_t)tok*Hn;
    float* dst = g_dec + (size_t)row*Hn;
    for(int k=threadIdx.x;k<Hn;k+=blockDim.x) dst[k]=src[k];
}

// ---------------- build H = tanh(e + d + b_j) rows as bf16 ----------------
__global__ void build_h(const float* __restrict__ bj){
    int r = blockIdx.x;              // row = bt*65 + u
    int bt = r / U1, u = r - bt*U1;
    int b = bt / Tn;
    const float* e = g_e + (size_t)bt*Jn;
    const float* d = g_d + (size_t)(b*U1+u)*Jn;
    __nv_bfloat16* h = g_Hbuf + (size_t)r*Jn;
    int k = threadIdx.x*4;           // 128 threads * 4 = 512
    float4 ev = *(const float4*)(e+k);
    float4 dv = *(const float4*)(d+k);
    float4 bv = *(const float4*)(bj+k);
    __nv_bfloat162 o0 = __floats2bfloat162_rn(tanhf(ev.x+dv.x+bv.x), tanhf(ev.y+dv.y+bv.y));
    __nv_bfloat162 o1 = __floats2bfloat162_rn(tanhf(ev.z+dv.z+bv.z), tanhf(ev.w+dv.w+bv.w));
    uint2 packed;
    packed.x = *(unsigned*)&o0;
    packed.y = *(unsigned*)&o1;
    *(uint2*)(h+k) = packed;
}

// ---------------- big GEMM: (66560 x 1024) = H(bf16) @ W_out, fused stats ----------------
__global__ __launch_bounds__(256,2) void big_gemm(const float* __restrict__ Wout,
                                                  const float* __restrict__ bout,
                                                  const int* __restrict__ targets){
    __shared__ __align__(16) float As[8][128];
    __shared__ __align__(16) float Bs[8][128];
    int tid = threadIdx.x;
    int tx = tid & 15, ty = tid >> 4;
    int rowBase = blockIdx.y * 128;
    int colBase = blockIdx.x * 128;
    float acc[8][8];
    #pragma unroll
    for(int i=0;i<8;i++)
        #pragma unroll
        for(int j=0;j<8;j++) acc[i][j]=0.f;

    int am = tid >> 1;
    int ak = (tid & 1) * 4;
    const __nv_bfloat16* Aptr = g_Hbuf + (size_t)(rowBase + am)*Jn + ak;
    int bk = tid >> 5;
    int bn = (tid & 31) * 4;
    const float* Bptr = Wout + (size_t)bk*Vn + colBase + bn;

    for(int k0=0;k0<Jn;k0+=8){
        uint2 araw = *(const uint2*)(Aptr + k0);
        __nv_bfloat162 a01 = *(__nv_bfloat162*)&araw.x;
        __nv_bfloat162 a23 = *(__nv_bfloat162*)&araw.y;
        float2 f01 = __bfloat1622float2(a01);
        float2 f23 = __bfloat1622float2(a23);
        As[ak+0][am] = f01.x;
        As[ak+1][am] = f01.y;
        As[ak+2][am] = f23.x;
        As[ak+3][am] = f23.y;
        float4 brow = *(const float4*)(Bptr + (size_t)k0*Vn);
        *(float4*)&Bs[bk][bn] = brow;
        __syncthreads();
        #pragma unroll
        for(int kk=0;kk<8;kk++){
            float4 a0 = *(float4*)&As[kk][ty*8];
            float4 a1 = *(float4*)&As[kk][ty*8+4];
            float4 b0 = *(float4*)&Bs[kk][tx*8];
            float4 b1 = *(float4*)&Bs[kk][tx*8+4];
            float a[8] = {a0.x,a0.y,a0.z,a0.w,a1.x,a1.y,a1.z,a1.w};
            float b[8] = {b0.x,b0.y,b0.z,b0.w,b1.x,b1.y,b1.z,b1.w};
            #pragma unroll
            for(int i=0;i<8;i++)
                #pragma unroll
                for(int j=0;j<8;j++) acc[i][j] = fmaf(a[i], b[j], acc[i][j]);
        }
        __syncthreads();
    }

    // Fused epilogue: per-row (chunk of 128 cols) max + sumexp, plus blank/target logits.
    float bo[8];
    #pragma unroll
    for(int j=0;j<8;j++) bo[j] = bout[colBase + tx*8 + j];
    #pragma unroll
    for(int i=0;i<8;i++){
        int row = rowBase + ty*8 + i;
        float v[8];
        float m = -3.4e38f;
        #pragma unroll
        for(int j=0;j<8;j++){ v[j] = acc[i][j] + bo[j]; m = fmaxf(m, v[j]); }
        #pragma unroll
        for(int o=8;o>=1;o>>=1) m = fmaxf(m, __shfl_xor_sync(0xffffffffu, m, o));
        float s = 0.f;
        #pragma unroll
        for(int j=0;j<8;j++) s += __expf(v[j]-m);
        #pragma unroll
        for(int o=8;o>=1;o>>=1) s += __shfl_xor_sync(0xffffffffu, s, o);
        if(tx==0){
            g_cmax[row*8 + blockIdx.x] = m;
            g_csum[row*8 + blockIdx.x] = s;
            if(blockIdx.x==0) g_l0[row] = v[0];
        }
        int bt = row / U1;
        int u = row - bt*U1;
        if(u < Un){
            int b = bt / Tn;
            int tgt = targets[b*Un + u];
            if((tgt >> 7) == (int)blockIdx.x){
                int lc = tgt & 127;
                if((lc >> 3) == tx) g_lt[row] = v[lc & 7];
            }
        }
    }
}

// ---------------- combine chunk stats -> blank_lp / lbl_lp ----------------
__global__ void combine_k(const int* __restrict__ tgt_lens){
    int r = blockIdx.x*256 + threadIdx.x;
    if(r >= NROWS) return;
    float M = -3.4e38f;
    #pragma unroll
    for(int c=0;c<8;c++) M = fmaxf(M, g_cmax[r*8+c]);
    float S = 0.f;
    #pragma unroll
    for(int c=0;c<8;c++) S += g_csum[r*8+c]*__expf(g_cmax[r*8+c]-M);
    float lse = M + logf(S);
    g_blank[r] = g_l0[r] - lse;
    int bt = r / U1, u = r - bt*U1;
    int b = bt / Tn;
    if(u < Un) g_lbl[bt*Un+u] = (u < tgt_lens[b]) ? (g_lt[r]-lse) : NEGF;
}

__global__ void zero_out(float* out){ if(threadIdx.x==0) out[0]=0.f; }

// ---------------- RNN-T forward DP: anti-diagonal wavefront ----------------
__global__ void dp_kernel(const int* __restrict__ in_lens, const int* __restrict__ tgt_lens,
                          float* __restrict__ out){
    int b = blockIdx.x;
    __shared__ float buf[2][U1];
    __shared__ float fin;
    int u = threadIdx.x;
    int tl = in_lens[b]-1;
    int uf = tgt_lens[b];
    for(int n=0;n<Tn+Un;n++){        // 320 diagonals (covers t+u up to 319)
        float* cur = buf[n&1];
        const float* prev = buf[(n&1)^1];
        if(u <= Un){
            int t = n - u;
            if(t >= 0 && t < Tn){
                float val;
                if(t==0 && u==0)      val = 0.f;
                else if(t==0)         val = prev[u-1] + g_lbl[(b*Tn+0)*Un + (u-1)];
                else if(u==0)         val = prev[0]   + g_blank[(b*Tn + t-1)*U1 + 0];
                else                  val = lae(prev[u]   + g_blank[(b*Tn+t-1)*U1 + u],
                                               prev[u-1] + g_lbl[(b*Tn+t)*Un + (u-1)]);
                cur[u] = val;
                if(t==tl && u==uf) fin = val + g_blank[(b*Tn+t)*U1 + u];
            }
        }
        __syncthreads();
    }
    if(threadIdx.x==0) atomicAdd(out, -fin * (1.0f/Bn));
}

// ---------------- launch ----------------
extern "C" void kernel_launch(void* const* d_in, const int* in_sizes, int n_in,
                              void* d_out, int out_size){
    (void)in_sizes; (void)n_in; (void)out_size;
    const float* inputs  = (const float*)d_in[0];
    const float* W_enc   = (const float*)d_in[1];
    const float* emb     = (const float*)d_in[2];
    const float* W_jenc  = (const float*)d_in[3];
    const float* W_jdec  = (const float*)d_in[4];
    const float* b_j     = (const float*)d_in[5];
    const float* W_out   = (const float*)d_in[6];
    const float* b_out   = (const float*)d_in[7];
    const int*   targets = (const int*)d_in[8];
    const int*   in_lens = (const int*)d_in[9];
    const int*   tgt_lens= (const int*)d_in[10];
    float* out = (float*)d_out;

    void *p_enc, *p_e, *p_dec, *p_d;
    cudaGetSymbolAddress(&p_enc, g_enc);
    cudaGetSymbolAddress(&p_e,   g_e);
    cudaGetSymbolAddress(&p_dec, g_dec);
    cudaGetSymbolAddress(&p_d,   g_d);

    gather_dec<<<Bn*U1, 128>>>(emb, targets);
    // enc = inputs(1024,80) @ W_enc(80,512)
    sgemm64<<<dim3(Hn/64, (Bn*Tn)/64), 256>>>(inputs, W_enc, (float*)p_enc, Bn*Tn, Hn, Fn);
    // e = enc @ W_jenc(512,512)
    sgemm64<<<dim3(Jn/64, (Bn*Tn)/64), 256>>>((const float*)p_enc, W_jenc, (float*)p_e, Bn*Tn, Jn, Hn);
    // d = dec(260,512) @ W_jdec(512,512)
    sgemm64<<<dim3(Jn/64, (Bn*U1+63)/64), 256>>>((const float*)p_dec, W_jdec, (float*)p_d, Bn*U1, Jn, Hn);
    build_h<<<NROWS, 128>>>(b_j);
    big_gemm<<<dim3(Vn/128, NROWS/128), 256>>>(W_out, b_out, targets);
    combine_k<<<(NROWS+255)/256, 256>>>(tgt_lens);
    zero_out<<<1, 32>>>(out);
    dp_kernel<<<Bn, 128>>>(in_lens, tgt_lens, out);
}

// round 3
// speedup vs baseline: 4.1389x; 4.1389x over previous
#include <cuda_runtime.h>
#include <cuda_bf16.h>
#include <math.h>
#include <cstdint>

// Problem constants
#define Bn 4
#define Tn 256
#define Un 64
#define U1 65
#define Vn 1024
#define Fn 80
#define Hn 512
#define Jn 512
#define NROWS (Bn*Tn*U1)   // 66560 = 520*128
#define NEGF (-1e30f)

// ---------------- scratch (static __device__, allocation-free) ----------------
__device__ float g_Wcomb[Fn*Jn];                 // W_enc @ W_jenc (80x512)
__device__ float g_e  [Bn*Tn*Jn];                // (1024, 512)
__device__ float g_dec[Bn*U1*Hn];                // (260, 512)
__device__ float g_d  [Bn*U1*Jn];                // (260, 512)
__device__ __nv_bfloat16 g_Hbuf[(size_t)NROWS*Jn];   // tanh rows, bf16
__device__ __nv_bfloat16 g_Wt[(size_t)Vn*Jn];        // W_out^T bf16, [V][J] K-major
__device__ float g_cmax[NROWS*16];
__device__ float g_csum[NROWS*16];
__device__ float g_l0[NROWS];
__device__ float g_lt[NROWS];
__device__ float g_blank[NROWS];
__device__ float g_lbl[Bn*Tn*Un];

__device__ __forceinline__ float lae(float a, float b){
    float m = fmaxf(a,b);
    return m + log1pf(__expf(fminf(a,b) - m));
}
__device__ __forceinline__ uint32_t s2u(const void* p){
    uint32_t a;
    asm("{ .reg .u64 t; cvta.to.shared.u64 t, %1; cvt.u32.u64 %0, t; }" : "=r"(a) : "l"(p));
    return a;
}

// ---------------- small tiled SGEMM: C(M,N) = A(M,K) @ B(K,N), 32x32 tiles ----------------
__global__ void gemm32(const float* __restrict__ A, const float* __restrict__ B,
                       float* __restrict__ C, int M, int N, int K){
    __shared__ float As[32][33];
    __shared__ float Bs[32][33];
    int tid = threadIdx.x;
    int tx = tid & 15, ty = tid >> 4;
    int rowBase = blockIdx.y*32, colBase = blockIdx.x*32;
    float acc[2][2] = {};
    for(int k0=0;k0<K;k0+=32){
        #pragma unroll
        for(int i=0;i<4;i++){
            int idx = i*256+tid;
            int m = idx>>5, k = idx&31;
            int gm = rowBase+m, gk = k0+k;
            As[m][k] = (gm<M && gk<K) ? A[(size_t)gm*K+gk] : 0.f;
            int kb = idx>>5, n = idx&31;
            int gkb = k0+kb, gn = colBase+n;
            Bs[kb][n] = (gkb<K && gn<N) ? B[(size_t)gkb*N+gn] : 0.f;
        }
        __syncthreads();
        #pragma unroll
        for(int kk=0;kk<32;kk++){
            float a0 = As[ty*2+0][kk], a1 = As[ty*2+1][kk];
            float b0 = Bs[kk][tx*2+0], b1 = Bs[kk][tx*2+1];
            acc[0][0] = fmaf(a0,b0,acc[0][0]);
            acc[0][1] = fmaf(a0,b1,acc[0][1]);
            acc[1][0] = fmaf(a1,b0,acc[1][0]);
            acc[1][1] = fmaf(a1,b1,acc[1][1]);
        }
        __syncthreads();
    }
    #pragma unroll
    for(int i=0;i<2;i++){
        int gm = rowBase+ty*2+i;
        if(gm<M)
            #pragma unroll
            for(int j=0;j<2;j++){
                int gn = colBase+tx*2+j;
                if(gn<N) C[(size_t)gm*N+gn]=acc[i][j];
            }
    }
}

// ---------------- gather decoder embedding rows ----------------
__global__ void gather_dec(const float* __restrict__ emb, const int* __restrict__ targets){
    int row = blockIdx.x;            // 0..259 = b*65+u
    int b = row / U1, u = row - b*U1;
    int tok = (u==0) ? 0 : targets[b*Un + (u-1)];
    const float* src = emb + (size_t)tok*Hn;
    float* dst = g_dec + (size_t)row*Hn;
    for(int k=threadIdx.x;k<Hn;k+=blockDim.x) dst[k]=src[k];
}

// ---------------- build H = tanh(e + d + b_j) rows as bf16 ----------------
__global__ void build_h(const float* __restrict__ bj){
    int r = blockIdx.x;              // row = bt*65 + u
    int bt = r / U1, u = r - bt*U1;
    int b = bt / Tn;
    const float* e = g_e + (size_t)bt*Jn;
    const float* d = g_d + (size_t)(b*U1+u)*Jn;
    __nv_bfloat16* h = g_Hbuf + (size_t)r*Jn;
    int k = threadIdx.x*4;           // 128 threads * 4 = 512
    float4 ev = *(const float4*)(e+k);
    float4 dv = *(const float4*)(d+k);
    float4 bv = *(const float4*)(bj+k);
    __nv_bfloat162 o0 = __floats2bfloat162_rn(tanhf(ev.x+dv.x+bv.x), tanhf(ev.y+dv.y+bv.y));
    __nv_bfloat162 o1 = __floats2bfloat162_rn(tanhf(ev.z+dv.z+bv.z), tanhf(ev.w+dv.w+bv.w));
    uint2 packed;
    packed.x = *(unsigned*)&o0;
    packed.y = *(unsigned*)&o1;
    *(uint2*)(h+k) = packed;
}

// ---------------- transpose W_out (J,V) fp32 -> g_Wt (V,J) bf16 ----------------
__global__ void wtrans(const float* __restrict__ W){
    __shared__ float t[32][33];
    int v0 = blockIdx.x*32, j0 = blockIdx.y*32;
    for(int i=threadIdx.y;i<32;i+=8)
        t[i][threadIdx.x] = W[(size_t)(j0+i)*Vn + v0 + threadIdx.x];
    __syncthreads();
    for(int i=threadIdx.y;i<32;i+=8)
        g_Wt[(size_t)(v0+i)*Jn + j0 + threadIdx.x] = __float2bfloat16(t[threadIdx.x][i]);
}

// ---------------- big GEMM via mma.sync bf16 + fused softmax stats ----------------
// CTA 128x128x(K=512), BK=32, 8 warps (4 m x 2 n), warp tile 32x64.
// SMEM rows padded to 80B (20 words): zero bank conflicts for fragment LDS.
#define ROWW 20
__global__ __launch_bounds__(256) void big_hmma(const float* __restrict__ bout,
                                                const int* __restrict__ targets){
    __shared__ __align__(16) uint32_t smA[2][128*ROWW];
    __shared__ __align__(16) uint32_t smB[2][128*ROWW];
    int tid = threadIdx.x, wid = tid>>5, lane = tid&31;
    int g = lane>>2, tg = lane&3;
    int warp_m = wid & 3, warp_n = wid >> 2;
    int rowBase = blockIdx.y*128;
    int nBase   = blockIdx.x*128;

    float acc[2][8][4];
    #pragma unroll
    for(int mt=0;mt<2;mt++)
        #pragma unroll
        for(int nt=0;nt<8;nt++)
            #pragma unroll
            for(int c=0;c<4;c++) acc[mt][nt][c]=0.f;

    uint32_t saddrA[2], saddrB[2];
    saddrA[0]=s2u(&smA[0][0]); saddrA[1]=s2u(&smA[1][0]);
    saddrB[0]=s2u(&smB[0][0]); saddrB[1]=s2u(&smB[1][0]);
    int ldr = tid>>2, ldc = tid&3;                 // 256 threads -> 64 rows x 4 chunks
    const char* gA = (const char*)(g_Hbuf + (size_t)(rowBase+ldr)*Jn + ldc*8);
    const char* gB = (const char*)(g_Wt   + (size_t)(nBase +ldr)*Jn + ldc*8);

    #define LOAD_TILE(buf, kt) do{ \
        uint32_t da = saddrA[buf] + ldr*80 + ldc*16; \
        uint32_t db = saddrB[buf] + ldr*80 + ldc*16; \
        unsigned long long pa = __cvta_generic_to_global(gA + (kt)*64); \
        unsigned long long pb = __cvta_generic_to_global(gB + (kt)*64); \
        asm volatile("cp.async.cg.shared.global [%0], [%1], 16;" :: "r"(da), "l"(pa)); \
        asm volatile("cp.async.cg.shared.global [%0], [%1], 16;" :: "r"(da + 64*80), "l"(pa + 64*1024)); \
        asm volatile("cp.async.cg.shared.global [%0], [%1], 16;" :: "r"(db), "l"(pb)); \
        asm volatile("cp.async.cg.shared.global [%0], [%1], 16;" :: "r"(db + 64*80), "l"(pb + 64*1024)); \
        asm volatile("cp.async.commit_group;"); \
    }while(0)

    LOAD_TILE(0, 0);
    for(int kt=0;kt<16;kt++){
        if(kt<15){
            LOAD_TILE((kt+1)&1, kt+1);
            asm volatile("cp.async.wait_group 1;");
        } else {
            asm volatile("cp.async.wait_group 0;");
        }
        __syncthreads();
        const uint32_t* A32 = &smA[kt&1][0];
        const uint32_t* B32 = &smB[kt&1][0];
        #pragma unroll
        for(int ks=0;ks<2;ks++){
            uint32_t af[2][4], bf[8][2];
            #pragma unroll
            for(int mt=0;mt<2;mt++){
                int r0 = warp_m*32 + mt*16;
                af[mt][0] = A32[(r0+g  )*ROWW + ks*8 + tg];
                af[mt][1] = A32[(r0+8+g)*ROWW + ks*8 + tg];
                af[mt][2] = A32[(r0+g  )*ROWW + ks*8 + tg + 4];
                af[mt][3] = A32[(r0+8+g)*ROWW + ks*8 + tg + 4];
            }
            #pragma unroll
            for(int nt=0;nt<8;nt++){
                int n0 = warp_n*64 + nt*8;
                bf[nt][0] = B32[(n0+g)*ROWW + ks*8 + tg];
                bf[nt][1] = B32[(n0+g)*ROWW + ks*8 + tg + 4];
            }
            #pragma unroll
            for(int mt=0;mt<2;mt++)
                #pragma unroll
                for(int nt=0;nt<8;nt++)
                    asm volatile(
                        "mma.sync.aligned.m16n8k16.row.col.f32.bf16.bf16.f32 "
                        "{%0,%1,%2,%3}, {%4,%5,%6,%7}, {%8,%9}, {%0,%1,%2,%3};"
                        : "+f"(acc[mt][nt][0]), "+f"(acc[mt][nt][1]),
                          "+f"(acc[mt][nt][2]), "+f"(acc[mt][nt][3])
                        : "r"(af[mt][0]),"r"(af[mt][1]),"r"(af[mt][2]),"r"(af[mt][3]),
                          "r"(bf[nt][0]),"r"(bf[nt][1]));
        }
        __syncthreads();
    }
    #undef LOAD_TILE

    // ---- fused epilogue: per-row chunk (64 cols per warp) max / sumexp ----
    int chunk = blockIdx.x*2 + warp_n;            // 16 chunks of 64 cols
    int colw = nBase + warp_n*64;
    float br[8][2];
    #pragma unroll
    for(int nt=0;nt<8;nt++){
        br[nt][0] = bout[colw + nt*8 + tg*2];
        br[nt][1] = bout[colw + nt*8 + tg*2 + 1];
    }
    #pragma unroll
    for(int mt=0;mt<2;mt++){
        #pragma unroll
        for(int half=0;half<2;half++){
            int row = rowBase + warp_m*32 + mt*16 + half*8 + g;
            float v[16];
            float m = -3.4e38f;
            #pragma unroll
            for(int nt=0;nt<8;nt++){
                v[nt*2]   = acc[mt][nt][half*2]   + br[nt][0];
                v[nt*2+1] = acc[mt][nt][half*2+1] + br[nt][1];
                m = fmaxf(m, fmaxf(v[nt*2], v[nt*2+1]));
            }
            float s = 0.f;
            #pragma unroll
            for(int j=0;j<16;j++) s += __expf(v[j]-m);
            #pragma unroll
            for(int o=1;o<4;o<<=1){
                float om = __shfl_xor_sync(0xffffffffu, m, o);
                float os = __shfl_xor_sync(0xffffffffu, s, o);
                float nm = fmaxf(m, om);
                s = s*__expf(m-nm) + os*__expf(om-nm);
                m = nm;
            }
            if(tg==0){
                g_cmax[row*16 + chunk] = m;
                g_csum[row*16 + chunk] = s;
                if(chunk==0) g_l0[row] = v[0];    // global col 0 (blank)
            }
            int bt = row / U1, u = row - bt*U1;
            if(u < Un){
                int b = bt / Tn;
                int tgt = targets[b*Un + u];
                int lc = tgt - colw;
                if(lc >= 0 && lc < 64){
                    int nt = lc>>3, cc = lc&7;
                    if((cc>>1)==tg) g_lt[row] = v[nt*2 + (cc&1)];
                }
            }
        }
    }
}

// ---------------- combine chunk stats -> blank_lp / lbl_lp ----------------
__global__ void combine_k(const int* __restrict__ tgt_lens){
    int r = blockIdx.x*256 + threadIdx.x;
    if(r >= NROWS) return;
    float M = -3.4e38f;
    #pragma unroll
    for(int c=0;c<16;c++) M = fmaxf(M, g_cmax[r*16+c]);
    float S = 0.f;
    #pragma unroll
    for(int c=0;c<16;c++) S += g_csum[r*16+c]*__expf(g_cmax[r*16+c]-M);
    float lse = M + logf(S);
    g_blank[r] = g_l0[r] - lse;
    int bt = r / U1, u = r - bt*U1;
    int b = bt / Tn;
    if(u < Un) g_lbl[bt*Un+u] = (u < tgt_lens[b]) ? (g_lt[r]-lse) : NEGF;
}

__global__ void zero_out(float* out){ if(threadIdx.x==0) out[0]=0.f; }

// ---------------- RNN-T forward DP: wavefront over SMEM-resident tables ----------------
#define DP_SMEM ((Tn*U1 + Tn*Un)*4)   // 132096 bytes
__global__ void dp_kernel(const int* __restrict__ in_lens, const int* __restrict__ tgt_lens,
                          float* __restrict__ out){
    extern __shared__ float sm[];
    float* s_blank = sm;               // Tn*U1
    float* s_lbl   = sm + Tn*U1;       // Tn*Un
    int b = blockIdx.x;
    for(int i=threadIdx.x;i<Tn*U1;i+=blockDim.x) s_blank[i] = g_blank[b*Tn*U1 + i];
    for(int i=threadIdx.x;i<Tn*Un;i+=blockDim.x) s_lbl[i]   = g_lbl[b*Tn*Un + i];
    __shared__ float buf[2][U1];
    __shared__ float fin;
    __syncthreads();
    int u = threadIdx.x;
    int tl = in_lens[b]-1;
    int uf = tgt_lens[b];
    int lim = tl + uf;
    for(int n=0;n<=lim;n++){
        float* cur = buf[n&1];
        const float* prev = buf[(n&1)^1];
        if(u <= Un){
            int t = n - u;
            if(t >= 0 && t < Tn){
                float val;
                if(t==0 && u==0)      val = 0.f;
                else if(t==0)         val = prev[u-1] + s_lbl[u-1];
                else if(u==0)         val = prev[0]   + s_blank[(t-1)*U1];
                else                  val = lae(prev[u]   + s_blank[(t-1)*U1 + u],
                                               prev[u-1] + s_lbl[t*Un + (u-1)]);
                cur[u] = val;
                if(t==tl && u==uf) fin = val + s_blank[t*U1 + u];
            }
        }
        __syncthreads();
    }
    if(threadIdx.x==0) atomicAdd(out, -fin * (1.0f/Bn));
}

// ---------------- launch ----------------
extern "C" void kernel_launch(void* const* d_in, const int* in_sizes, int n_in,
                              void* d_out, int out_size){
    (void)in_sizes; (void)n_in; (void)out_size;
    const float* inputs  = (const float*)d_in[0];
    const float* W_enc   = (const float*)d_in[1];
    const float* emb     = (const float*)d_in[2];
    const float* W_jenc  = (const float*)d_in[3];
    const float* W_jdec  = (const float*)d_in[4];
    const float* b_j     = (const float*)d_in[5];
    const float* W_out   = (const float*)d_in[6];
    const float* b_out   = (const float*)d_in[7];
    const int*   targets = (const int*)d_in[8];
    const int*   in_lens = (const int*)d_in[9];
    const int*   tgt_lens= (const int*)d_in[10];
    float* out = (float*)d_out;

    cudaFuncSetAttribute(dp_kernel, cudaFuncAttributeMaxDynamicSharedMemorySize, DP_SMEM);

    void *p_wc, *p_e, *p_dec, *p_d;
    cudaGetSymbolAddress(&p_wc,  g_Wcomb);
    cudaGetSymbolAddress(&p_e,   g_e);
    cudaGetSymbolAddress(&p_dec, g_dec);
    cudaGetSymbolAddress(&p_d,   g_d);

    // W_comb = W_enc(80,512) @ W_jenc(512,512)
    gemm32<<<dim3(Jn/32, (Fn+31)/32), 256>>>(W_enc, W_jenc, (float*)p_wc, Fn, Jn, Hn);
    gather_dec<<<Bn*U1, 128>>>(emb, targets);
    wtrans<<<dim3(Vn/32, Jn/32), dim3(32,8)>>>(W_out);
    // e = inputs(1024,80) @ W_comb(80,512)
    gemm32<<<dim3(Jn/32, (Bn*Tn)/32), 256>>>(inputs, (const float*)p_wc, (float*)p_e, Bn*Tn, Jn, Fn);
    // d = dec(260,512) @ W_jdec(512,512)
    gemm32<<<dim3(Jn/32, (Bn*U1+31)/32), 256>>>((const float*)p_dec, W_jdec, (float*)p_d, Bn*U1, Jn, Hn);
    build_h<<<NROWS, 128>>>(b_j);
    big_hmma<<<dim3(Vn/128, NROWS/128), 256>>>(b_out, targets);
    combine_k<<<(NROWS+255)/256, 256>>>(tgt_lens);
    zero_out<<<1, 32>>>(out);
    dp_kernel<<<Bn, 128, DP_SMEM>>>(in_lens, tgt_lens, out);
}

// round 4
// speedup vs baseline: 4.6556x; 1.1248x over previous
#include <cuda_runtime.h>
#include <cuda_bf16.h>
#include <math.h>
#include <cstdint>

// Problem constants
#define Bn 4
#define Tn 256
#define Un 64
#define U1 65
#define Vn 1024
#define Fn 80
#define Hn 512
#define Jn 512
#define NROWS (Bn*Tn*U1)   // 66560 = 520*128
#define NEGF (-1e30f)

// ---------------- scratch (static __device__, allocation-free) ----------------
__device__ float g_Wcomb[Fn*Jn];                 // W_enc @ W_jenc (80x512)
__device__ float g_e  [Bn*Tn*Jn];                // (1024, 512)
__device__ float g_dec[Bn*U1*Hn];                // (260, 512)
__device__ float g_d  [Bn*U1*Jn];                // (260, 512)
__device__ __nv_bfloat16 g_Wt[(size_t)Vn*Jn];    // W_out^T bf16, [V][J] K-major
__device__ float g_blank[NROWS];
__device__ float g_lbl[Bn*Tn*Un];

__device__ __forceinline__ float lae(float a, float b){
    float m = fmaxf(a,b);
    return m + log1pf(__expf(fminf(a,b) - m));
}
__device__ __forceinline__ uint32_t s2u(const void* p){
    uint32_t a;
    asm("{ .reg .u64 t; cvta.to.shared.u64 t, %1; cvt.u32.u64 %0, t; }" : "=r"(a) : "l"(p));
    return a;
}

// ---------------- small tiled SGEMM: C(M,N) = A(M,K) @ B(K,N), 32x32 tiles ----------------
__global__ void gemm32(const float* __restrict__ A, const float* __restrict__ B,
                       float* __restrict__ C, int M, int N, int K){
    __shared__ float As[32][33];
    __shared__ float Bs[32][33];
    int tid = threadIdx.x;
    int tx = tid & 15, ty = tid >> 4;
    int rowBase = blockIdx.y*32, colBase = blockIdx.x*32;
    float acc[2][2] = {};
    for(int k0=0;k0<K;k0+=32){
        #pragma unroll
        for(int i=0;i<4;i++){
            int idx = i*256+tid;
            int m = idx>>5, k = idx&31;
            int gm = rowBase+m, gk = k0+k;
            As[m][k] = (gm<M && gk<K) ? A[(size_t)gm*K+gk] : 0.f;
            int kb = idx>>5, n = idx&31;
            int gkb = k0+kb, gn = colBase+n;
            Bs[kb][n] = (gkb<K && gn<N) ? B[(size_t)gkb*N+gn] : 0.f;
        }
        __syncthreads();
        #pragma unroll
        for(int kk=0;kk<32;kk++){
            float a0 = As[ty*2+0][kk], a1 = As[ty*2+1][kk];
            float b0 = Bs[kk][tx*2+0], b1 = Bs[kk][tx*2+1];
            acc[0][0] = fmaf(a0,b0,acc[0][0]);
            acc[0][1] = fmaf(a0,b1,acc[0][1]);
            acc[1][0] = fmaf(a1,b0,acc[1][0]);
            acc[1][1] = fmaf(a1,b1,acc[1][1]);
        }
        __syncthreads();
    }
    #pragma unroll
    for(int i=0;i<2;i++){
        int gm = rowBase+ty*2+i;
        if(gm<M)
            #pragma unroll
            for(int j=0;j<2;j++){
                int gn = colBase+tx*2+j;
                if(gn<N) C[(size_t)gm*N+gn]=acc[i][j];
            }
    }
}

// ---------------- gather decoder embedding rows ----------------
__global__ void gather_dec(const float* __restrict__ emb, const int* __restrict__ targets){
    int row = blockIdx.x;            // 0..259 = b*65+u
    int b = row / U1, u = row - b*U1;
    int tok = (u==0) ? 0 : targets[b*Un + (u-1)];
    const float* src = emb + (size_t)tok*Hn;
    float* dst = g_dec + (size_t)row*Hn;
    for(int k=threadIdx.x;k<Hn;k+=blockDim.x) dst[k]=src[k];
}

// ---------------- transpose W_out (J,V) fp32 -> g_Wt (V,J) bf16 ----------------
__global__ void wtrans(const float* __restrict__ W){
    __shared__ float t[32][33];
    int v0 = blockIdx.x*32, j0 = blockIdx.y*32;
    for(int i=threadIdx.y;i<32;i+=8)
        t[i][threadIdx.x] = W[(size_t)(j0+i)*Vn + v0 + threadIdx.x];
    __syncthreads();
    for(int i=threadIdx.y;i<32;i+=8)
        g_Wt[(size_t)(v0+i)*Jn + j0 + threadIdx.x] = __float2bfloat16(t[threadIdx.x][i]);
}

// ================= fused joint kernel =================
// 520 CTAs, each owns 128 rows x all 1024 cols.
// SMEM: A full-K tile (tanh(e+d+b_j) bf16) [16 kt][128 rows][80B],
//       B 3 x [128 n][80B] cp.async ring, stats region.
// 8 warps (4 m x 2 n), warp tile 32x64 per 128-col chunk, 8 chunks.
#define AOFFB 0
#define BOFFB (16*128*80)             // 163840
#define SOFFB (BOFFB + 3*128*80)      // +30720 = 194560
#define BIG_SMEM (SOFFB + 3584)       // 198144
__global__ void __launch_bounds__(256) big_fused(const float* __restrict__ bout,
                                                 const float* __restrict__ bj,
                                                 const int* __restrict__ targets,
                                                 const int* __restrict__ tgt_lens){
    extern __shared__ char sm[];
    uint32_t sA = s2u(sm) + AOFFB;
    uint32_t sB = s2u(sm) + BOFFB;
    float* pm  = (float*)(sm + SOFFB);          // [2][128]
    float* ps  = pm + 256;                      // [2][128]
    float* pvt = ps + 256;                      // [2][128]
    float* pv0 = pvt + 256;                     // [128]

    int tid = threadIdx.x, wid = tid>>5, lane = tid&31;
    int g = lane>>2, tg = lane&3;
    int warp_m = wid & 3, warp_n = wid >> 2;
    int rowBase = blockIdx.x*128;

    // ---- prologue: build H = tanh(e+d+bj) bf16 directly into A smem ----
    {
        int r = tid>>1;
        int half = tid&1;
        int row = rowBase + r;
        int bt = row / U1, u = row - bt*U1, b = bt >> 8;
        const float4* ep = (const float4*)(g_e + (size_t)bt*Jn + half*256);
        const float4* dp = (const float4*)(g_d + (size_t)(b*U1+u)*Jn + half*256);
        const float4* bp = (const float4*)(bj + half*256);
        #pragma unroll 8
        for(int i=0;i<64;i++){
            float4 e4 = ep[i], d4 = dp[i], b4 = bp[i];
            __nv_bfloat162 o0 = __floats2bfloat162_rn(tanhf(e4.x+d4.x+b4.x), tanhf(e4.y+d4.y+b4.y));
            __nv_bfloat162 o1 = __floats2bfloat162_rn(tanhf(e4.z+d4.z+b4.z), tanhf(e4.w+d4.w+b4.w));
            int k = half*256 + i*4;
            int kt = k>>5, w = (k&31)>>1;
            uint32_t addr = sA + kt*10240 + r*80 + w*4;
            uint32_t w0 = *(unsigned*)&o0, w1 = *(unsigned*)&o1;
            asm volatile("st.shared.v2.b32 [%0], {%1,%2};" :: "r"(addr), "r"(w0), "r"(w1));
        }
    }

    // per-slot row info (slot = mt*2 + half)
    int rows4[4], tgt4[4], u4[4];
    #pragma unroll
    for(int mt=0;mt<2;mt++)
        #pragma unroll
        for(int half=0;half<2;half++){
            int s = mt*2+half;
            int rl = warp_m*32 + mt*16 + half*8 + g;
            int row = rowBase + rl;
            rows4[s] = rl;
            int bt = row / U1, u = row - bt*U1, b = bt >> 8;
            u4[s] = u;
            tgt4[s] = (u < Un) ? targets[b*Un + u] : -1;
        }

    // ldmatrix base addresses
    uint32_t aBase[2];
    #pragma unroll
    for(int mt=0;mt<2;mt++)
        aBase[mt] = sA + (warp_m*32 + mt*16 + (lane&7) + ((lane>>3)&1)*8)*80
                       + ((lane>>4)&1)*16;
    uint32_t bBase[4];
    #pragma unroll
    for(int j=0;j<4;j++)
        bBase[j] = sB + (warp_n*64 + j*16 + (lane&7) + ((lane>>4)&1)*8)*80
                      + ((lane>>3)&1)*16;

    float m4[4] = {-3.4e38f,-3.4e38f,-3.4e38f,-3.4e38f};
    float s4[4] = {0.f,0.f,0.f,0.f};
    float vt4[4] = {-3.4e38f,-3.4e38f,-3.4e38f,-3.4e38f};
    float v04[4] = {0.f,0.f,0.f,0.f};

    int brow = tid>>1;                  // B loader: 2x16B per thread
    int bc0  = (tid&1)*2;
    #define LOADB(buf, nch, kt) do{ \
        unsigned long long p = __cvta_generic_to_global( \
            (const char*)g_Wt + ((size_t)((nch)*128 + brow))*1024 + (kt)*64 + bc0*16); \
        uint32_t d = sB + (buf)*10240 + brow*80 + bc0*16; \
        asm volatile("cp.async.cg.shared.global [%0], [%1], 16;" :: "r"(d), "l"(p)); \
        asm volatile("cp.async.cg.shared.global [%0], [%1], 16;" :: "r"(d+16), "l"(p+16)); \
    }while(0)

    for(int nch=0;nch<8;nch++){
        float acc[2][8][4];
        #pragma unroll
        for(int mt=0;mt<2;mt++)
            #pragma unroll
            for(int nt=0;nt<8;nt++)
                #pragma unroll
                for(int c=0;c<4;c++) acc[mt][nt][c]=0.f;

        __syncthreads();   // prologue/H stores done; prior-chunk B reads done
        LOADB(0, nch, 0);
        asm volatile("cp.async.commit_group;");
        LOADB(1, nch, 1);
        asm volatile("cp.async.commit_group;");

        for(int kt=0;kt<16;kt++){
            asm volatile("cp.async.wait_group 1;");
            __syncthreads();
            // issue kt+2
            if(kt<14){ LOADB((kt+2)%3, nch, kt+2); }
            asm volatile("cp.async.commit_group;");

            uint32_t aoff = kt*10240;
            uint32_t boff = (kt%3)*10240 - (uint32_t)BOFFB + (uint32_t)BOFFB; // buf offset within B
            uint32_t bbuf = (kt%3)*10240;
            #pragma unroll
            for(int ks=0;ks<2;ks++){
                uint32_t af[2][4];
                #pragma unroll
                for(int mt=0;mt<2;mt++)
                    asm volatile("ldmatrix.sync.aligned.m8n8.x4.shared.b16 {%0,%1,%2,%3}, [%4];"
                        : "=r"(af[mt][0]),"=r"(af[mt][1]),"=r"(af[mt][2]),"=r"(af[mt][3])
                        : "r"(aBase[mt] + aoff + ks*32));
                uint32_t bf[8][2];
                #pragma unroll
                for(int j=0;j<4;j++){
                    uint32_t b0,b1,b2,b3;
                    asm volatile("ldmatrix.sync.aligned.m8n8.x4.shared.b16 {%0,%1,%2,%3}, [%4];"
                        : "=r"(b0),"=r"(b1),"=r"(b2),"=r"(b3)
                        : "r"(bBase[j] + bbuf + ks*32));
                    bf[2*j][0]=b0; bf[2*j][1]=b1; bf[2*j+1][0]=b2; bf[2*j+1][1]=b3;
                }
                #pragma unroll
                for(int mt=0;mt<2;mt++)
                    #pragma unroll
                    for(int nt=0;nt<8;nt++)
                        asm volatile(
                            "mma.sync.aligned.m16n8k16.row.col.f32.bf16.bf16.f32 "
                            "{%0,%1,%2,%3}, {%4,%5,%6,%7}, {%8,%9}, {%0,%1,%2,%3};"
                            : "+f"(acc[mt][nt][0]), "+f"(acc[mt][nt][1]),
                              "+f"(acc[mt][nt][2]), "+f"(acc[mt][nt][3])
                            : "r"(af[mt][0]),"r"(af[mt][1]),"r"(af[mt][2]),"r"(af[mt][3]),
                              "r"(bf[nt][0]),"r"(bf[nt][1]));
            }
            (void)boff;
        }

        // ---- chunk epilogue: running softmax stats ----
        int colw = nch*128 + warp_n*64;
        float br0[8], br1[8];
        #pragma unroll
        for(int nt=0;nt<8;nt++){
            br0[nt] = bout[colw + nt*8 + tg*2];
            br1[nt] = bout[colw + nt*8 + tg*2 + 1];
        }
        #pragma unroll
        for(int mt=0;mt<2;mt++){
            #pragma unroll
            for(int half=0;half<2;half++){
                int slot = mt*2+half;
                float v[16];
                float cm = -3.4e38f;
                #pragma unroll
                for(int nt=0;nt<8;nt++){
                    v[nt*2]   = acc[mt][nt][half*2]   + br0[nt];
                    v[nt*2+1] = acc[mt][nt][half*2+1] + br1[nt];
                    cm = fmaxf(cm, fmaxf(v[nt*2], v[nt*2+1]));
                }
                float nm = fmaxf(m4[slot], cm);
                float s = s4[slot]*__expf(m4[slot]-nm);
                #pragma unroll
                for(int j=0;j<16;j++) s += __expf(v[j]-nm);
                m4[slot] = nm; s4[slot] = s;
                int lc = tgt4[slot] - colw;
                if(lc >= 0 && lc < 64){
                    int nt = lc>>3, cc = lc&7;
                    if((cc>>1)==tg) vt4[slot] = v[nt*2 + (cc&1)];
                }
                if(nch==0 && warp_n==0 && tg==0) v04[slot] = v[0];
            }
        }
    }
    #undef LOADB

    // ---- cross-lane (quad) + cross-warp_n combine ----
    #pragma unroll
    for(int slot=0;slot<4;slot++){
        #pragma unroll
        for(int o=1;o<4;o<<=1){
            float om = __shfl_xor_sync(0xffffffffu, m4[slot], o);
            float os = __shfl_xor_sync(0xffffffffu, s4[slot], o);
            float ov = __shfl_xor_sync(0xffffffffu, vt4[slot], o);
            float nm = fmaxf(m4[slot], om);
            s4[slot] = s4[slot]*__expf(m4[slot]-nm) + os*__expf(om-nm);
            m4[slot] = nm;
            vt4[slot] = fmaxf(vt4[slot], ov);
        }
        if(tg==0){
            int rl = rows4[slot];
            pm [warp_n*128 + rl] = m4[slot];
            ps [warp_n*128 + rl] = s4[slot];
            pvt[warp_n*128 + rl] = vt4[slot];
            if(warp_n==0) pv0[rl] = v04[slot];
        }
    }
    __syncthreads();
    if(tid < 128){
        int r = tid;
        int row = rowBase + r;
        float m0 = pm[r], m1 = pm[128+r];
        float nm = fmaxf(m0, m1);
        float s = ps[r]*__expf(m0-nm) + ps[128+r]*__expf(m1-nm);
        float lse = nm + logf(s);
        g_blank[row] = pv0[r] - lse;
        int bt = row / U1, u = row - bt*U1;
        if(u < Un){
            int b = bt >> 8;
            float vt = fmaxf(pvt[r], pvt[128+r]);
            g_lbl[bt*Un+u] = (u < tgt_lens[b]) ? (vt - lse) : NEGF;
        }
    }
}

__global__ void zero_out(float* out){ if(threadIdx.x==0) out[0]=0.f; }

// ---------------- RNN-T forward DP: wavefront over SMEM-resident tables ----------------
#define DP_SMEM ((Tn*U1 + Tn*Un)*4)   // 132096 bytes
__global__ void dp_kernel(const int* __restrict__ in_lens, const int* __restrict__ tgt_lens,
                          float* __restrict__ out){
    extern __shared__ float smf[];
    float* s_blank = smf;              // Tn*U1
    float* s_lbl   = smf + Tn*U1;      // Tn*Un
    int b = blockIdx.x;
    for(int i=threadIdx.x;i<Tn*U1;i+=blockDim.x) s_blank[i] = g_blank[b*Tn*U1 + i];
    for(int i=threadIdx.x;i<Tn*Un;i+=blockDim.x) s_lbl[i]   = g_lbl[b*Tn*Un + i];
    __shared__ float buf[2][U1];
    __shared__ float fin;
    __syncthreads();
    int u = threadIdx.x;
    int tl = in_lens[b]-1;
    int uf = tgt_lens[b];
    int lim = tl + uf;
    for(int n=0;n<=lim;n++){
        float* cur = buf[n&1];
        const float* prev = buf[(n&1)^1];
        if(u <= Un){
            int t = n - u;
            if(t >= 0 && t < Tn){
                float val;
                if(t==0 && u==0)      val = 0.f;
                else if(t==0)         val = prev[u-1] + s_lbl[u-1];
                else if(u==0)         val = prev[0]   + s_blank[(t-1)*U1];
                else                  val = lae(prev[u]   + s_blank[(t-1)*U1 + u],
                                               prev[u-1] + s_lbl[t*Un + (u-1)]);
                cur[u] = val;
                if(t==tl && u==uf) fin = val + s_blank[t*U1 + u];
            }
        }
        __syncthreads();
    }
    if(threadIdx.x==0) atomicAdd(out, -fin * (1.0f/Bn));
}

// ---------------- launch ----------------
extern "C" void kernel_launch(void* const* d_in, const int* in_sizes, int n_in,
                              void* d_out, int out_size){
    (void)in_sizes; (void)n_in; (void)out_size;
    const float* inputs  = (const float*)d_in[0];
    const float* W_enc   = (const float*)d_in[1];
    const float* emb     = (const float*)d_in[2];
    const float* W_jenc  = (const float*)d_in[3];
    const float* W_jdec  = (const float*)d_in[4];
    const float* b_j     = (const float*)d_in[5];
    const float* W_out   = (const float*)d_in[6];
    const float* b_out   = (const float*)d_in[7];
    const int*   targets = (const int*)d_in[8];
    const int*   in_lens = (const int*)d_in[9];
    const int*   tgt_lens= (const int*)d_in[10];
    float* out = (float*)d_out;

    cudaFuncSetAttribute(big_fused, cudaFuncAttributeMaxDynamicSharedMemorySize, BIG_SMEM);
    cudaFuncSetAttribute(dp_kernel, cudaFuncAttributeMaxDynamicSharedMemorySize, DP_SMEM);

    void *p_wc, *p_e, *p_dec, *p_d;
    cudaGetSymbolAddress(&p_wc,  g_Wcomb);
    cudaGetSymbolAddress(&p_e,   g_e);
    cudaGetSymbolAddress(&p_dec, g_dec);
    cudaGetSymbolAddress(&p_d,   g_d);

    // W_comb = W_enc(80,512) @ W_jenc(512,512)
    gemm32<<<dim3(Jn/32, (Fn+31)/32), 256>>>(W_enc, W_jenc, (float*)p_wc, Fn, Jn, Hn);
    gather_dec<<<Bn*U1, 128>>>(emb, targets);
    wtrans<<<dim3(Vn/32, Jn/32), dim3(32,8)>>>(W_out);
    // e = inputs(1024,80) @ W_comb(80,512)
    gemm32<<<dim3(Jn/32, (Bn*Tn)/32), 256>>>(inputs, (const float*)p_wc, (float*)p_e, Bn*Tn, Jn, Fn);
    // d = dec(260,512) @ W_jdec(512,512)
    gemm32<<<dim3(Jn/32, (Bn*U1+31)/32), 256>>>((const float*)p_dec, W_jdec, (float*)p_d, Bn*U1, Jn, Hn);
    big_fused<<<520, 256, BIG_SMEM>>>(b_out, b_j, targets, tgt_lens);
    zero_out<<<1, 32>>>(out);
    dp_kernel<<<Bn, 128, DP_SMEM>>>(in_lens, tgt_lens, out);
}